// round 13
// baseline (speedup 1.0000x reference)
#include <cuda_runtime.h>
#include <cuda_fp16.h>
#include <math.h>
#include <stdint.h>

// ---------------- problem constants ----------------------------------------
#define T_TOK 12000          // B*S/K tokens
#define D_IN  2560           // ENC*K
#define HID   512
#define LLM   2048
#define NE    8
#define NTOP  2
#define TWO   (T_TOK*NTOP)   // 24000 (token,slot) pairs

// ---------------- static device scratch ------------------------------------
__device__ __half g_nx[(size_t)T_TOK * D_IN];       // LN'd input (fp16, GEMM)
__device__ __half g_act[(size_t)T_TOK * HID];       // shared swiglu (fp16)
__device__ __half g_shared[(size_t)T_TOK * LLM];    // shared out (fp16)
__device__ __half g_eact[(size_t)TWO * HID];        // expert swiglu (fp16)
__device__ __half g_eo[(size_t)TWO * LLM];          // expert out (fp16)
__device__ __half g_w12s[(size_t)2 * HID * D_IN];   // fp16 weights
__device__ __half g_w3s[(size_t)LLM * HID];
__device__ __half g_w12e[(size_t)NE * 2 * HID * D_IN];
__device__ __half g_w3e[(size_t)NE * LLM * HID];
__device__ int   g_idx[TWO];
__device__ float g_w[TWO];
__device__ int   g_perm[TWO];
__device__ float g_permw[TWO];
__device__ int   g_pos[TWO];
__device__ int   g_cnt[NE];
__device__ int   g_cur[NE];
__device__ int   g_off[NE + 1];

// ---------------- PTX helpers (sm_80-era; safe for plain sm_100) -----------
__device__ __forceinline__ uint32_t smem_u32(const void* p) {
    uint32_t a;
    asm("{ .reg .u64 t; cvta.to.shared.u64 t, %1; cvt.u32.u64 %0, t; }" : "=r"(a) : "l"(p));
    return a;
}
__device__ __forceinline__ void cpa16(uint32_t dst, const void* src, uint32_t srcsz) {
    asm volatile("cp.async.cg.shared.global [%0], [%1], 16, %2;"
                 :: "r"(dst), "l"(src), "r"(srcsz) : "memory");
}
#define CP_COMMIT() asm volatile("cp.async.commit_group;" ::: "memory")
#define CP_WAIT1()  asm volatile("cp.async.wait_group 1;" ::: "memory")

__device__ __forceinline__ void ldsm4(uint32_t& r0, uint32_t& r1, uint32_t& r2, uint32_t& r3,
                                      uint32_t addr) {
    asm volatile("ldmatrix.sync.aligned.m8n8.x4.shared.b16 {%0,%1,%2,%3}, [%4];"
                 : "=r"(r0), "=r"(r1), "=r"(r2), "=r"(r3) : "r"(addr));
}
__device__ __forceinline__ void mma_f16(float* c,
                                        uint32_t a0, uint32_t a1, uint32_t a2, uint32_t a3,
                                        uint32_t b0, uint32_t b1) {
    asm volatile(
        "mma.sync.aligned.m16n8k16.row.col.f32.f16.f16.f32 "
        "{%0,%1,%2,%3}, {%4,%5,%6,%7}, {%8,%9}, {%0,%1,%2,%3};"
        : "+f"(c[0]), "+f"(c[1]), "+f"(c[2]), "+f"(c[3])
        : "r"(a0), "r"(a1), "r"(a2), "r"(a3), "r"(b0), "r"(b1));
}

// ---------------- smem geometry ---------------------------------------------
// CTA tile 128x128, BK=64. 144B row stride -> conflict-free STS + ldsm.
#define ASTRB    144
#define A_BYTES  (128 * ASTRB)            // 18432
#define STAGE_B  (256 * ASTRB)            // 36864 (A 128 rows + B 128 rows)
#define SMEM_DYN (3 * STAGE_B)            // 110592 -> 2 CTAs/SM
#define EPI_STR  132                      // fp32 epilogue stage stride

// ---------------- kernel 0: convert weights to fp16 (+ zero counters) -------
__global__ __launch_bounds__(256) void cvt_weights(
    const float4* __restrict__ s12, const float4* __restrict__ s3,
    const float4* __restrict__ e12, const float4* __restrict__ e3)
{
    if (blockIdx.x == 0 && threadIdx.x < NE) {
        g_cnt[threadIdx.x] = 0;
        g_cur[threadIdx.x] = 0;
    }
    const int N1 = 2 * HID * D_IN / 4;
    const int N2 = LLM * HID / 4;
    const int N3 = NE * 2 * HID * D_IN / 4;
    const int N4 = NE * LLM * HID / 4;
    const int total = N1 + N2 + N3 + N4;
    for (int i = blockIdx.x * blockDim.x + threadIdx.x; i < total;
         i += gridDim.x * blockDim.x) {
        float4 v; __half2* dst;
        int j = i;
        if (j < N1)              { v = s12[j]; dst = (__half2*)g_w12s + 2 * j; }
        else if ((j -= N1) < N2) { v = s3[j];  dst = (__half2*)g_w3s  + 2 * j; }
        else if ((j -= N2) < N3) { v = e12[j]; dst = (__half2*)g_w12e + 2 * j; }
        else { j -= N3;           v = e3[j];  dst = (__half2*)g_w3e  + 2 * j; }
        dst[0] = __floats2half2_rn(v.x, v.y);
        dst[1] = __floats2half2_rn(v.z, v.w);
    }
}

// ---------------- kernel 1: fused LN_pre + router ----------------------------
__global__ __launch_bounds__(256) void ln_router_kernel(
    const float* __restrict__ x,
    const float* __restrict__ lng, const float* __restrict__ lnb,
    const float* __restrict__ rw,  const float* __restrict__ rb)
{
    extern __shared__ __align__(16) char smem[];
    float* s_rw = (float*)smem;                 // [NE][D_IN] fp32 = 80KB
    __shared__ int s_cnt[NE];
    int tid = threadIdx.x;
    if (tid < NE) s_cnt[tid] = 0;
    for (int i = tid; i < NE * D_IN / 4; i += 256)
        ((float4*)s_rw)[i] = ((const float4*)rw)[i];
    __syncthreads();

    int wid = tid >> 5, lane = tid & 31;
    for (int it = 0; it < 8; it++) {
        int t = blockIdx.x * 64 + wid * 8 + it;
        if (t >= T_TOK) break;
        const float2* row = (const float2*)(x + (size_t)t * D_IN);
        float2 h[40];
        float sum = 0.f, sq = 0.f;
        #pragma unroll
        for (int j = 0; j < 40; j++) {
            h[j] = row[lane + j * 32];
            sum += h[j].x + h[j].y;
            sq  += h[j].x * h[j].x + h[j].y * h[j].y;
        }
        #pragma unroll
        for (int o = 16; o > 0; o >>= 1) {
            sum += __shfl_xor_sync(0xFFFFFFFFu, sum, o);
            sq  += __shfl_xor_sync(0xFFFFFFFFu, sq,  o);
        }
        float m = sum * (1.f / D_IN);
        float var = sq * (1.f / D_IN) - m * m;
        float rinv = rsqrtf(var + 1e-6f);

        __half2* nxr = (__half2*)(g_nx + (size_t)t * D_IN);
        #pragma unroll
        for (int j = 0; j < 40; j++) {
            float2 gv = ((const float2*)lng)[lane + j * 32];
            float2 bv = ((const float2*)lnb)[lane + j * 32];
            h[j].x = (h[j].x - m) * rinv * gv.x + bv.x;
            h[j].y = (h[j].y - m) * rinv * gv.y + bv.y;
            nxr[lane + j * 32] = __floats2half2_rn(h[j].x, h[j].y);
        }

        float lg[NE];
        #pragma unroll
        for (int e = 0; e < NE; e++) {
            const float2* w2 = (const float2*)(s_rw + e * D_IN);
            float acc = 0.f;
            #pragma unroll
            for (int j = 0; j < 40; j++) {
                float2 wv = w2[lane + j * 32];
                acc = fmaf(h[j].x, wv.x, acc);
                acc = fmaf(h[j].y, wv.y, acc);
            }
            #pragma unroll
            for (int o = 16; o > 0; o >>= 1)
                acc += __shfl_down_sync(0xFFFFFFFFu, acc, o);
            lg[e] = acc;
        }
        if (lane == 0) {
            float p[NE];
            float mx = lg[0] + rb[0];
            #pragma unroll
            for (int e = 0; e < NE; e++) { p[e] = lg[e] + rb[e]; mx = fmaxf(mx, p[e]); }
            float se = 0.f;
            #pragma unroll
            for (int e = 0; e < NE; e++) { p[e] = __expf(p[e] - mx); se += p[e]; }
            float rse = 1.f / se;
            #pragma unroll
            for (int e = 0; e < NE; e++) p[e] *= rse;
            int i0 = 0;
            #pragma unroll
            for (int e = 1; e < NE; e++) if (p[e] > p[i0]) i0 = e;
            int i1 = (i0 == 0) ? 1 : 0;
            #pragma unroll
            for (int e = 0; e < NE; e++) if (e != i0 && p[e] > p[i1]) i1 = e;
            float s2 = p[i0] + p[i1] + 1e-20f;
            g_idx[2 * t + 0] = i0; g_w[2 * t + 0] = p[i0] / s2;
            g_idx[2 * t + 1] = i1; g_w[2 * t + 1] = p[i1] / s2;
            atomicAdd(&s_cnt[i0], 1);
            atomicAdd(&s_cnt[i1], 1);
        }
    }
    __syncthreads();
    if (tid < NE && s_cnt[tid]) atomicAdd(&g_cnt[tid], s_cnt[tid]);
}

// ---------------- kernel 2/3: scan + permutation (aggregated atomics) -------
__global__ void scan_kernel() {
    if (threadIdx.x == 0) {
        int o = 0;
        for (int e = 0; e < NE; e++) { g_off[e] = o; o += g_cnt[e]; }
        g_off[NE] = o;
    }
}
__global__ __launch_bounds__(256) void build_kernel() {
    __shared__ int s_cur[NE], s_base[NE];
    int tid = threadIdx.x;
    if (tid < NE) s_cur[tid] = 0;
    __syncthreads();
    int t = blockIdx.x * 256 + tid;
    int e2[2], lp[2];
    if (t < T_TOK) {
        #pragma unroll
        for (int k = 0; k < NTOP; k++) {
            e2[k] = g_idx[2 * t + k];
            lp[k] = atomicAdd(&s_cur[e2[k]], 1);
        }
    }
    __syncthreads();
    if (tid < NE) s_base[tid] = s_cur[tid] ? atomicAdd(&g_cur[tid], s_cur[tid]) : 0;
    __syncthreads();
    if (t < T_TOK) {
        #pragma unroll
        for (int k = 0; k < NTOP; k++) {
            int p = g_off[e2[k]] + s_base[e2[k]] + lp[k];
            g_perm[p]  = t;
            g_permw[p] = g_w[2 * t + k];
            g_pos[2 * t + k] = p;
        }
    }
}

// ============================================================================
// fp16 mma core: CTA 128x128, BK=64, 256 threads, 8 warps (4x2), warp 32x64
// 3-stage pipeline, 110.6KB smem -> 2 CTAs/SM (independent barriers overlap)
// ============================================================================
#define GEMM_FRAGS                                                            \
    const int lane = threadIdx.x & 31, wid = threadIdx.x >> 5;                \
    const int wm = (wid >> 1) * 32, wn = (wid & 1) * 64;                      \
    const int l16 = lane & 15, lh = lane >> 4;                                \
    const int bg = lane >> 3;                                                 \
    const int b_row = ((bg & 1) << 3) + (lane & 7), b_ch = bg >> 1;

#define LOAD_FRAGS(A, B, abase, bbase, step)                                  \
    _Pragma("unroll")                                                         \
    for (int mf = 0; mf < 2; mf++)                                            \
        ldsm4((A)[mf][0], (A)[mf][1], (A)[mf][2], (A)[mf][3],                 \
              (abase) + (wm + mf * 16 + l16) * ASTRB + ((step) * 2 + lh) * 16); \
    _Pragma("unroll")                                                         \
    for (int nb = 0; nb < 4; nb++)                                            \
        ldsm4((B)[nb][0], (B)[nb][1], (B)[nb][2], (B)[nb][3],                 \
              (bbase) + (wn + nb * 16 + b_row) * ASTRB + ((step) * 2 + b_ch) * 16);

#define MMA_FRAGS(A, B)                                                       \
    _Pragma("unroll")                                                         \
    for (int mf = 0; mf < 2; mf++)                                            \
        _Pragma("unroll")                                                     \
        for (int nb = 0; nb < 4; nb++) {                                      \
            mma_f16(acc[mf][2 * nb],     (A)[mf][0], (A)[mf][1], (A)[mf][2], (A)[mf][3], (B)[nb][0], (B)[nb][2]); \
            mma_f16(acc[mf][2 * nb + 1], (A)[mf][0], (A)[mf][1], (A)[mf][2], (A)[mf][3], (B)[nb][1], (B)[nb][3]); \
        }

#define GEMM_MAINLOOP(NK)                                                     \
    uint32_t af[2][4], bf[4][4];                                              \
    for (int kt = 0; kt < (NK); kt++) {                                       \
        CP_WAIT1();                                                           \
        __syncthreads();                                                      \
        uint32_t abase = sbase + (kt % 3) * STAGE_B;                          \
        uint32_t bbase = abase + A_BYTES;                                     \
        if (kt + 2 < (NK)) fill((kt + 2) % 3, (kt + 2) * 64);                 \
        else CP_COMMIT();                                                     \
        _Pragma("unroll")                                                     \
        for (int step = 0; step < 4; step++) {                                \
            LOAD_FRAGS(af, bf, abase, bbase, step)                            \
            MMA_FRAGS(af, bf)                                                 \
        }                                                                     \
    }

#define GEMM_EPI_STAGE(st)                                                    \
    {                                                                         \
        const int cg = lane >> 2, ct = lane & 3;                              \
        _Pragma("unroll")                                                     \
        for (int mf = 0; mf < 2; mf++) {                                      \
            int row = wm + mf * 16 + cg;                                      \
            _Pragma("unroll")                                                 \
            for (int nf = 0; nf < 8; nf++) {                                  \
                int col = wn + nf * 8 + ct * 2;                               \
                *(float2*)((st) + row * EPI_STR + col)       = make_float2(acc[mf][nf][0], acc[mf][nf][1]); \
                *(float2*)((st) + (row + 8) * EPI_STR + col) = make_float2(acc[mf][nf][2], acc[mf][nf][3]); \
            }                                                                 \
        }                                                                     \
    }

// ============================================================================
// kernel 4: GEMM w12 + fused SwiGLU. CTA: 128 rows x 64 act cols
//   (B rows 0-63 = gate w12[colBase+..], 64-127 = val w12[HID+colBase+..])
// ============================================================================
__global__ __launch_bounds__(256, 2) void gemm12_mma()
{
    const int z = blockIdx.z;
    int rowStart, nrows;
    const __half* W;
    if (z == 0) {
        rowStart = blockIdx.y * 128;
        if (rowStart >= T_TOK) return;
        nrows = min(128, T_TOK - rowStart);
        W = g_w12s;
    } else {
        int e = z - 1;
        int re = g_off[e + 1];
        rowStart = g_off[e] + blockIdx.y * 128;
        if (rowStart >= re) return;
        nrows = min(128, re - rowStart);
        W = g_w12e + (size_t)e * (2 * HID) * D_IN;
    }
    const int colBase = blockIdx.x * 64;    // act column tile

    extern __shared__ __align__(16) char smem[];
    __shared__ int s_perm[128];
    const uint32_t sbase = smem_u32(smem);
    const int tid = threadIdx.x;

    if (z && tid < 128)
        s_perm[tid] = (tid < nrows) ? g_perm[rowStart + tid] : 0;
    __syncthreads();

    // A: 256 threads cover 128 rows x 2 chunks of 64B
    const int arow = tid >> 1;
    const uint32_t avalid = (arow < nrows) ? 16 : 0;
    const __half* srcA = (z ? (g_nx + (size_t)s_perm[arow] * D_IN)
                            : (g_nx + (size_t)(rowStart + min(arow, nrows - 1)) * D_IN))
                         + (tid & 1) * 32;
    // B: 256 threads cover 128 rows x 2 chunks of 64B
    const int brow = tid >> 1;
    const int wrow = (brow < 64) ? (colBase + brow) : (HID + colBase + (brow - 64));
    const __half* srcB = W + (size_t)wrow * D_IN + (tid & 1) * 32;
    const uint32_t adst0 = sbase + arow * ASTRB + (tid & 1) * 64;
    const uint32_t bdst0 = sbase + A_BYTES + brow * ASTRB + (tid & 1) * 64;

    auto fill = [&](int s, int k0) {
        uint32_t ad = adst0 + s * STAGE_B;
        #pragma unroll
        for (int j = 0; j < 4; j++) cpa16(ad + j * 16, srcA + k0 + j * 8, avalid);
        uint32_t bd = bdst0 + s * STAGE_B;
        #pragma unroll
        for (int j = 0; j < 4; j++) cpa16(bd + j * 16, srcB + k0 + j * 8, 16);
        CP_COMMIT();
    };

    fill(0, 0); fill(1, 64);

    float acc[2][8][4] = {};
    GEMM_FRAGS
    GEMM_MAINLOOP(D_IN / 64)
    __syncthreads();

    float* st = (float*)smem;   // [128][EPI_STR]
    GEMM_EPI_STAGE(st)
    __syncthreads();

    __half* Out = z ? g_eact : g_act;
    #pragma unroll
    for (int i = 0; i < 8; i++) {
        int f = tid + i * 256;
        int r = f >> 4, c4 = f & 15;            // 16 x 4-half chunks = 64 cols
        if (r < nrows) {
            float4 gg = *(float4*)(st + r * EPI_STR + c4 * 4);
            float4 vv = *(float4*)(st + r * EPI_STR + 64 + c4 * 4);
            __half2 h0 = __floats2half2_rn(gg.x / (1.f + __expf(-gg.x)) * vv.x,
                                           gg.y / (1.f + __expf(-gg.y)) * vv.y);
            __half2 h1 = __floats2half2_rn(gg.z / (1.f + __expf(-gg.z)) * vv.z,
                                           gg.w / (1.f + __expf(-gg.w)) * vv.w);
            uint32_t u0 = *(uint32_t*)&h0, u1 = *(uint32_t*)&h1;
            *(uint2*)(Out + (size_t)(rowStart + r) * HID + colBase + c4 * 4) =
                make_uint2(u0, u1);
        }
    }
}

// ============================================================================
// kernel 5: GEMM w3 (+ fused routing weight). CTA: 128 rows x 128 out cols
// ============================================================================
__global__ __launch_bounds__(256, 2) void gemm3_mma()
{
    const int z = blockIdx.z;
    int rowStart, nrows;
    const __half* W;
    if (z == 0) {
        rowStart = blockIdx.y * 128;
        if (rowStart >= T_TOK) return;
        nrows = min(128, T_TOK - rowStart);
        W = g_w3s;
    } else {
        int e = z - 1;
        int re = g_off[e + 1];
        rowStart = g_off[e] + blockIdx.y * 128;
        if (rowStart >= re) return;
        nrows = min(128, re - rowStart);
        W = g_w3e + (size_t)e * LLM * HID;
    }
    const int colBase = blockIdx.x * 128;
    const __half* Act = z ? g_eact : g_act;

    extern __shared__ __align__(16) char smem[];
    const uint32_t sbase = smem_u32(smem);
    const int tid = threadIdx.x;

    const int arow = tid >> 1;
    const uint32_t avalid = (arow < nrows) ? 16 : 0;
    const __half* srcA = Act + (size_t)(rowStart + min(arow, nrows - 1)) * HID + (tid & 1) * 32;
    const int brow = tid >> 1;
    const __half* srcB = W + (size_t)(colBase + brow) * HID + (tid & 1) * 32;
    const uint32_t adst0 = sbase + arow * ASTRB + (tid & 1) * 64;
    const uint32_t bdst0 = sbase + A_BYTES + brow * ASTRB + (tid & 1) * 64;

    auto fill = [&](int s, int k0) {
        uint32_t ad = adst0 + s * STAGE_B;
        #pragma unroll
        for (int j = 0; j < 4; j++) cpa16(ad + j * 16, srcA + k0 + j * 8, avalid);
        uint32_t bd = bdst0 + s * STAGE_B;
        #pragma unroll
        for (int j = 0; j < 4; j++) cpa16(bd + j * 16, srcB + k0 + j * 8, 16);
        CP_COMMIT();
    };

    fill(0, 0); fill(1, 64);

    float acc[2][8][4] = {};
    GEMM_FRAGS
    GEMM_MAINLOOP(HID / 64)
    __syncthreads();

    float* st = (float*)smem;   // [128][EPI_STR]
    GEMM_EPI_STAGE(st)
    __syncthreads();

    __half* Out = z ? g_eo : g_shared;
    #pragma unroll
    for (int i = 0; i < 8; i++) {
        int f = tid + i * 256;
        int r = f >> 4, ch = f & 15;            // 16 chunks of 8 halfs = 128 cols
        if (r < nrows) {
            float sc = z ? g_permw[rowStart + r] : 1.f;
            const float* s0 = st + r * EPI_STR + ch * 8;
            __half2 h0 = __floats2half2_rn(sc * s0[0], sc * s0[1]);
            __half2 h1 = __floats2half2_rn(sc * s0[2], sc * s0[3]);
            __half2 h2 = __floats2half2_rn(sc * s0[4], sc * s0[5]);
            __half2 h3 = __floats2half2_rn(sc * s0[6], sc * s0[7]);
            uint4 u;
            u.x = *(uint32_t*)&h0; u.y = *(uint32_t*)&h1;
            u.z = *(uint32_t*)&h2; u.w = *(uint32_t*)&h3;
            *(uint4*)(Out + (size_t)(rowStart + r) * LLM + colBase + ch * 8) = u;
        }
    }
}

// ---------------- kernel 6: combine + LN_post (fp16 inputs) ------------------
__device__ __forceinline__ void blockReduce2(float& sum, float& sq) {
    __shared__ float ss[8], sv[8];
    #pragma unroll
    for (int o = 16; o > 0; o >>= 1) {
        sum += __shfl_down_sync(0xFFFFFFFFu, sum, o);
        sq  += __shfl_down_sync(0xFFFFFFFFu, sq,  o);
    }
    int w = threadIdx.x >> 5, l = threadIdx.x & 31;
    if (l == 0) { ss[w] = sum; sv[w] = sq; }
    __syncthreads();
    if (w == 0) {
        sum = (l < 8) ? ss[l] : 0.f;
        sq  = (l < 8) ? sv[l] : 0.f;
        #pragma unroll
        for (int o = 4; o > 0; o >>= 1) {
            sum += __shfl_down_sync(0xFFFFFFFFu, sum, o);
            sq  += __shfl_down_sync(0xFFFFFFFFu, sq,  o);
        }
        if (l == 0) { ss[0] = sum; sv[0] = sq; }
    }
    __syncthreads();
    sum = ss[0]; sq = sv[0];
}

__global__ __launch_bounds__(256) void ln_post_kernel(
    const float* __restrict__ lng, const float* __restrict__ lnb,
    float* __restrict__ out)
{
    int t = blockIdx.x;
    int tid = threadIdx.x;
    int p0 = g_pos[2 * t + 0], p1 = g_pos[2 * t + 1];
    const __half2* sh = (const __half2*)(g_shared + (size_t)t * LLM);
    const __half2* e0 = (const __half2*)(g_eo + (size_t)p0 * LLM);
    const __half2* e1 = (const __half2*)(g_eo + (size_t)p1 * LLM);
    float2 v[4];
    float sum = 0.f, sq = 0.f;
    #pragma unroll
    for (int i = 0; i < 4; i++) {
        int j = tid + i * 256;          // half2 index, j < 1024
        float2 a = __half22float2(sh[j]);
        float2 b = __half22float2(e0[j]);
        float2 c = __half22float2(e1[j]);
        float2 val = make_float2(a.x + b.x + c.x, a.y + b.y + c.y);
        v[i] = val;
        sum += val.x + val.y;
        sq += val.x * val.x + val.y * val.y;
    }
    blockReduce2(sum, sq);
    float m = sum * (1.f / LLM);
    float var = sq * (1.f / LLM) - m * m;
    float rinv = rsqrtf(var + 1e-6f);
    float* orow = out + (size_t)t * LLM;
    #pragma unroll
    for (int i = 0; i < 4; i++) {
        int j = tid + i * 256;
        float2 gv = ((const float2*)lng)[j];
        float2 bv = ((const float2*)lnb)[j];
        float2 o;
        o.x = (v[i].x - m) * rinv * gv.x + bv.x;
        o.y = (v[i].y - m) * rinv * gv.y + bv.y;
        *(float2*)(orow + 2 * j) = o;
    }
}

// ---------------- launcher ----------------------------------------------------
extern "C" void kernel_launch(void* const* d_in, const int* in_sizes, int n_in,
                              void* d_out, int out_size)
{
    const float* x           = (const float*)d_in[0];
    const float* ln_pre_g    = (const float*)d_in[1];
    const float* ln_pre_b    = (const float*)d_in[2];
    const float* router_w    = (const float*)d_in[3];
    const float* router_b    = (const float*)d_in[4];
    const float* shared_w12  = (const float*)d_in[5];
    const float* shared_w3   = (const float*)d_in[6];
    const float* experts_w12 = (const float*)d_in[7];
    const float* experts_w3  = (const float*)d_in[8];
    const float* ln_post_g   = (const float*)d_in[9];
    const float* ln_post_b   = (const float*)d_in[10];
    float* out = (float*)d_out;

    const int RW_SMEM = NE * D_IN * 4;  // 80 KB
    cudaFuncSetAttribute(gemm12_mma, cudaFuncAttributeMaxDynamicSharedMemorySize, SMEM_DYN);
    cudaFuncSetAttribute(gemm3_mma,  cudaFuncAttributeMaxDynamicSharedMemorySize, SMEM_DYN);
    cudaFuncSetAttribute(ln_router_kernel, cudaFuncAttributeMaxDynamicSharedMemorySize, RW_SMEM);

    cvt_weights<<<4096, 256>>>((const float4*)shared_w12, (const float4*)shared_w3,
                               (const float4*)experts_w12, (const float4*)experts_w3);
    ln_router_kernel<<<(T_TOK + 63) / 64, 256, RW_SMEM>>>(x, ln_pre_g, ln_pre_b,
                                                          router_w, router_b);
    scan_kernel<<<1, 32>>>();
    build_kernel<<<(T_TOK + 255) / 256, 256>>>();

    const int MT = (T_TOK + 127) / 128;   // 94 (also covers worst-case expert)
    gemm12_mma<<<dim3(HID / 64, MT, NE + 1), 256, SMEM_DYN>>>();
    gemm3_mma <<<dim3(LLM / 128, MT, NE + 1), 256, SMEM_DYN>>>();

    ln_post_kernel<<<T_TOK, 256>>>(ln_post_g, ln_post_b, out);
}

// round 16
// speedup vs baseline: 1.1128x; 1.1128x over previous
#include <cuda_runtime.h>
#include <cuda_fp16.h>
#include <math.h>
#include <stdint.h>

// ---------------- problem constants ----------------------------------------
#define T_TOK 12000          // B*S/K tokens
#define D_IN  2560           // ENC*K
#define HID   512
#define LLM   2048
#define NE    8
#define NTOP  2
#define TWO   (T_TOK*NTOP)   // 24000 (token,slot) pairs

// ---------------- static device scratch ------------------------------------
__device__ __half g_nx[(size_t)T_TOK * D_IN];       // LN'd input (fp16, GEMM)
__device__ __half g_act[(size_t)T_TOK * HID];       // shared swiglu (fp16)
__device__ __half g_shared[(size_t)T_TOK * LLM];    // shared out (fp16)
__device__ __half g_eact[(size_t)TWO * HID];        // expert swiglu (fp16)
__device__ __half g_eo[(size_t)TWO * LLM];          // expert out (fp16)
__device__ __half g_w12s[(size_t)2 * HID * D_IN];   // fp16 weights
__device__ __half g_w3s[(size_t)LLM * HID];
__device__ __half g_w12e[(size_t)NE * 2 * HID * D_IN];
__device__ __half g_w3e[(size_t)NE * LLM * HID];
__device__ int   g_idx[TWO];
__device__ float g_w[TWO];
__device__ int   g_perm[TWO];
__device__ float g_permw[TWO];
__device__ int   g_pos[TWO];
__device__ int   g_cnt[NE];
__device__ int   g_cur[NE];
__device__ int   g_off[NE + 1];

// ---------------- PTX helpers (sm_80-era; safe for plain sm_100) -----------
__device__ __forceinline__ uint32_t smem_u32(const void* p) {
    uint32_t a;
    asm("{ .reg .u64 t; cvta.to.shared.u64 t, %1; cvt.u32.u64 %0, t; }" : "=r"(a) : "l"(p));
    return a;
}
__device__ __forceinline__ void cpa16(uint32_t dst, const void* src, uint32_t srcsz) {
    asm volatile("cp.async.cg.shared.global [%0], [%1], 16, %2;"
                 :: "r"(dst), "l"(src), "r"(srcsz) : "memory");
}
#define CP_COMMIT() asm volatile("cp.async.commit_group;" ::: "memory")
// wait_group 2: with groups 0..kt+2 committed at iter kt, this retires all but
// the 2 newest => group kt (the stage we are about to ldsm) is COMPLETE.
// (wait_group 3 was a race: stage kt could still be in flight. R14 lesson.)
#define CP_WAIT2()  asm volatile("cp.async.wait_group 2;" ::: "memory")

__device__ __forceinline__ void ldsm4(uint32_t& r0, uint32_t& r1, uint32_t& r2, uint32_t& r3,
                                      uint32_t addr) {
    asm volatile("ldmatrix.sync.aligned.m8n8.x4.shared.b16 {%0,%1,%2,%3}, [%4];"
                 : "=r"(r0), "=r"(r1), "=r"(r2), "=r"(r3) : "r"(addr));
}
__device__ __forceinline__ void mma_f16(float* c,
                                        uint32_t a0, uint32_t a1, uint32_t a2, uint32_t a3,
                                        uint32_t b0, uint32_t b1) {
    asm volatile(
        "mma.sync.aligned.m16n8k16.row.col.f32.f16.f16.f32 "
        "{%0,%1,%2,%3}, {%4,%5,%6,%7}, {%8,%9}, {%0,%1,%2,%3};"
        : "+f"(c[0]), "+f"(c[1]), "+f"(c[2]), "+f"(c[3])
        : "r"(a0), "r"(a1), "r"(a2), "r"(a3), "r"(b0), "r"(b1));
}

// ---------------- smem geometry ---------------------------------------------
#define ASTRB    144
#define A_BYTES  (128 * ASTRB)            // 18432
#define B_BYTES  (256 * ASTRB)            // 36864
#define STAGE_B  (A_BYTES + B_BYTES)      // 55296
#define SMEM_DYN (4 * STAGE_B)            // 221184, 4-stage pipeline
#define EPI_STR  264                      // fp32 epilogue stage stride

// ---------------- kernel 0: convert weights to fp16 (+ zero counters) -------
__global__ __launch_bounds__(256) void cvt_weights(
    const float4* __restrict__ s12, const float4* __restrict__ s3,
    const float4* __restrict__ e12, const float4* __restrict__ e3)
{
    if (blockIdx.x == 0 && threadIdx.x < NE) {
        g_cnt[threadIdx.x] = 0;
        g_cur[threadIdx.x] = 0;
    }
    const int N1 = 2 * HID * D_IN / 4;
    const int N2 = LLM * HID / 4;
    const int N3 = NE * 2 * HID * D_IN / 4;
    const int N4 = NE * LLM * HID / 4;
    const int total = N1 + N2 + N3 + N4;
    for (int i = blockIdx.x * blockDim.x + threadIdx.x; i < total;
         i += gridDim.x * blockDim.x) {
        float4 v; __half2* dst;
        int j = i;
        if (j < N1)              { v = s12[j]; dst = (__half2*)g_w12s + 2 * j; }
        else if ((j -= N1) < N2) { v = s3[j];  dst = (__half2*)g_w3s  + 2 * j; }
        else if ((j -= N2) < N3) { v = e12[j]; dst = (__half2*)g_w12e + 2 * j; }
        else { j -= N3;           v = e3[j];  dst = (__half2*)g_w3e  + 2 * j; }
        dst[0] = __floats2half2_rn(v.x, v.y);
        dst[1] = __floats2half2_rn(v.z, v.w);
    }
}

// ---------------- kernel 1: fused LN_pre + router ----------------------------
__global__ __launch_bounds__(256) void ln_router_kernel(
    const float* __restrict__ x,
    const float* __restrict__ lng, const float* __restrict__ lnb,
    const float* __restrict__ rw,  const float* __restrict__ rb)
{
    extern __shared__ __align__(16) char smem[];
    float* s_rw = (float*)smem;                 // [NE][D_IN] fp32 = 80KB
    __shared__ int s_cnt[NE];
    int tid = threadIdx.x;
    if (tid < NE) s_cnt[tid] = 0;
    for (int i = tid; i < NE * D_IN / 4; i += 256)
        ((float4*)s_rw)[i] = ((const float4*)rw)[i];
    __syncthreads();

    int wid = tid >> 5, lane = tid & 31;
    for (int it = 0; it < 8; it++) {
        int t = blockIdx.x * 64 + wid * 8 + it;
        if (t >= T_TOK) break;
        const float2* row = (const float2*)(x + (size_t)t * D_IN);
        float2 h[40];
        float sum = 0.f, sq = 0.f;
        #pragma unroll
        for (int j = 0; j < 40; j++) {
            h[j] = row[lane + j * 32];
            sum += h[j].x + h[j].y;
            sq  += h[j].x * h[j].x + h[j].y * h[j].y;
        }
        #pragma unroll
        for (int o = 16; o > 0; o >>= 1) {
            sum += __shfl_xor_sync(0xFFFFFFFFu, sum, o);
            sq  += __shfl_xor_sync(0xFFFFFFFFu, sq,  o);
        }
        float m = sum * (1.f / D_IN);
        float var = sq * (1.f / D_IN) - m * m;
        float rinv = rsqrtf(var + 1e-6f);

        __half2* nxr = (__half2*)(g_nx + (size_t)t * D_IN);
        #pragma unroll
        for (int j = 0; j < 40; j++) {
            float2 gv = ((const float2*)lng)[lane + j * 32];
            float2 bv = ((const float2*)lnb)[lane + j * 32];
            h[j].x = (h[j].x - m) * rinv * gv.x + bv.x;
            h[j].y = (h[j].y - m) * rinv * gv.y + bv.y;
            nxr[lane + j * 32] = __floats2half2_rn(h[j].x, h[j].y);
        }

        float lg[NE];
        #pragma unroll
        for (int e = 0; e < NE; e++) {
            const float2* w2 = (const float2*)(s_rw + e * D_IN);
            float acc = 0.f;
            #pragma unroll
            for (int j = 0; j < 40; j++) {
                float2 wv = w2[lane + j * 32];
                acc = fmaf(h[j].x, wv.x, acc);
                acc = fmaf(h[j].y, wv.y, acc);
            }
            #pragma unroll
            for (int o = 16; o > 0; o >>= 1)
                acc += __shfl_down_sync(0xFFFFFFFFu, acc, o);
            lg[e] = acc;
        }
        if (lane == 0) {
            float p[NE];
            float mx = lg[0] + rb[0];
            #pragma unroll
            for (int e = 0; e < NE; e++) { p[e] = lg[e] + rb[e]; mx = fmaxf(mx, p[e]); }
            float se = 0.f;
            #pragma unroll
            for (int e = 0; e < NE; e++) { p[e] = __expf(p[e] - mx); se += p[e]; }
            float rse = 1.f / se;
            #pragma unroll
            for (int e = 0; e < NE; e++) p[e] *= rse;
            int i0 = 0;
            #pragma unroll
            for (int e = 1; e < NE; e++) if (p[e] > p[i0]) i0 = e;
            int i1 = (i0 == 0) ? 1 : 0;
            #pragma unroll
            for (int e = 0; e < NE; e++) if (e != i0 && p[e] > p[i1]) i1 = e;
            float s2 = p[i0] + p[i1] + 1e-20f;
            g_idx[2 * t + 0] = i0; g_w[2 * t + 0] = p[i0] / s2;
            g_idx[2 * t + 1] = i1; g_w[2 * t + 1] = p[i1] / s2;
            atomicAdd(&s_cnt[i0], 1);
            atomicAdd(&s_cnt[i1], 1);
        }
    }
    __syncthreads();
    if (tid < NE && s_cnt[tid]) atomicAdd(&g_cnt[tid], s_cnt[tid]);
}

// ---------------- kernel 2/3: scan + permutation (aggregated atomics) -------
__global__ void scan_kernel() {
    if (threadIdx.x == 0) {
        int o = 0;
        for (int e = 0; e < NE; e++) { g_off[e] = o; o += g_cnt[e]; }
        g_off[NE] = o;
    }
}
__global__ __launch_bounds__(256) void build_kernel() {
    __shared__ int s_cur[NE], s_base[NE];
    int tid = threadIdx.x;
    if (tid < NE) s_cur[tid] = 0;
    __syncthreads();
    int t = blockIdx.x * 256 + tid;
    int e2[2], lp[2];
    if (t < T_TOK) {
        #pragma unroll
        for (int k = 0; k < NTOP; k++) {
            e2[k] = g_idx[2 * t + k];
            lp[k] = atomicAdd(&s_cur[e2[k]], 1);
        }
    }
    __syncthreads();
    if (tid < NE) s_base[tid] = s_cur[tid] ? atomicAdd(&g_cur[tid], s_cur[tid]) : 0;
    __syncthreads();
    if (t < T_TOK) {
        #pragma unroll
        for (int k = 0; k < NTOP; k++) {
            int p = g_off[e2[k]] + s_base[e2[k]] + lp[k];
            g_perm[p]  = t;
            g_permw[p] = g_w[2 * t + k];
            g_pos[2 * t + k] = p;
        }
    }
}

// ============================================================================
// fp16 mma core: CTA 128x256, BK=64, 512 threads, 16 warps (4x4), warp 32x64
// Early first-ldsm + safe wait_group 2.
// ============================================================================
#define GEMM_FRAGS                                                            \
    const int lane = threadIdx.x & 31, wid = threadIdx.x >> 5;                \
    const int wm = (wid >> 2) * 32, wn = (wid & 3) * 64;                      \
    const int l16 = lane & 15, lh = lane >> 4;                                \
    const int bg = lane >> 3;                                                 \
    const int b_row = ((bg & 1) << 3) + (lane & 7), b_ch = bg >> 1;

#define LOAD_FRAGS(A, B, abase, bbase, step)                                  \
    _Pragma("unroll")                                                         \
    for (int mf = 0; mf < 2; mf++)                                            \
        ldsm4((A)[mf][0], (A)[mf][1], (A)[mf][2], (A)[mf][3],                 \
              (abase) + (wm + mf * 16 + l16) * ASTRB + ((step) * 2 + lh) * 16); \
    _Pragma("unroll")                                                         \
    for (int nb = 0; nb < 4; nb++)                                            \
        ldsm4((B)[nb][0], (B)[nb][1], (B)[nb][2], (B)[nb][3],                 \
              (bbase) + (wn + nb * 16 + b_row) * ASTRB + ((step) * 2 + b_ch) * 16);

#define MMA_FRAGS(A, B)                                                       \
    _Pragma("unroll")                                                         \
    for (int mf = 0; mf < 2; mf++)                                            \
        _Pragma("unroll")                                                     \
        for (int nb = 0; nb < 4; nb++) {                                      \
            mma_f16(acc[mf][2 * nb],     (A)[mf][0], (A)[mf][1], (A)[mf][2], (A)[mf][3], (B)[nb][0], (B)[nb][2]); \
            mma_f16(acc[mf][2 * nb + 1], (A)[mf][0], (A)[mf][1], (A)[mf][2], (A)[mf][3], (B)[nb][1], (B)[nb][3]); \
        }

#define GEMM_MAINLOOP(NK)                                                     \
    uint32_t af[2][4], bf[4][4];                                              \
    for (int kt = 0; kt < (NK); kt++) {                                       \
        CP_WAIT2();                                                           \
        __syncthreads();                                                      \
        uint32_t abase = sbase + (kt & 3) * STAGE_B;                          \
        uint32_t bbase = abase + A_BYTES;                                     \
        LOAD_FRAGS(af, bf, abase, bbase, 0)                                   \
        if (kt + 3 < (NK)) fill((kt + 3) & 3, (kt + 3) * 64);                 \
        else CP_COMMIT();                                                     \
        MMA_FRAGS(af, bf)                                                     \
        _Pragma("unroll")                                                     \
        for (int step = 1; step < 4; step++) {                                \
            LOAD_FRAGS(af, bf, abase, bbase, step)                            \
            MMA_FRAGS(af, bf)                                                 \
        }                                                                     \
    }

#define GEMM_EPI_STAGE(st)                                                    \
    {                                                                         \
        const int cg = lane >> 2, ct = lane & 3;                              \
        _Pragma("unroll")                                                     \
        for (int mf = 0; mf < 2; mf++) {                                      \
            int row = wm + mf * 16 + cg;                                      \
            _Pragma("unroll")                                                 \
            for (int nf = 0; nf < 8; nf++) {                                  \
                int col = wn + nf * 8 + ct * 2;                               \
                *(float2*)((st) + row * EPI_STR + col)       = make_float2(acc[mf][nf][0], acc[mf][nf][1]); \
                *(float2*)((st) + (row + 8) * EPI_STR + col) = make_float2(acc[mf][nf][2], acc[mf][nf][3]); \
            }                                                                 \
        }                                                                     \
    }

// ============================================================================
// kernel 4: GEMM w12 + fused SwiGLU, merged shared(z=0)/expert(z=1..8)
// ============================================================================
__global__ __launch_bounds__(512, 1) void gemm12_mma()
{
    const int z = blockIdx.z;
    int rowStart, nrows;
    const __half* W;
    if (z == 0) {
        rowStart = blockIdx.y * 128;
        if (rowStart >= T_TOK) return;
        nrows = min(128, T_TOK - rowStart);
        W = g_w12s;
    } else {
        int e = z - 1;
        int re = g_off[e + 1];
        rowStart = g_off[e] + blockIdx.y * 128;
        if (rowStart >= re) return;
        nrows = min(128, re - rowStart);
        W = g_w12e + (size_t)e * (2 * HID) * D_IN;
    }
    const int colBase = blockIdx.x * 128;   // act column tile

    extern __shared__ __align__(16) char smem[];
    __shared__ int s_perm[128];
    const uint32_t sbase = smem_u32(smem);
    const int tid = threadIdx.x;

    if (z && tid < 128)
        s_perm[tid] = (tid < nrows) ? g_perm[rowStart + tid] : 0;
    __syncthreads();

    // A: 512 threads cover 128 rows x 4 chunks of 32B
    const int arow = tid >> 2;
    const uint32_t avalid = (arow < nrows) ? 16 : 0;
    const __half* srcA = (z ? (g_nx + (size_t)s_perm[arow] * D_IN)
                            : (g_nx + (size_t)(rowStart + min(arow, nrows - 1)) * D_IN))
                         + (tid & 3) * 16;
    // B: 512 threads cover 256 rows x 2 chunks of 64B
    const int brow = tid >> 1;
    const int wrow = (brow < 128) ? (colBase + brow) : (HID + colBase + (brow - 128));
    const __half* srcB = W + (size_t)wrow * D_IN + (tid & 1) * 32;
    const uint32_t adst0 = sbase + arow * ASTRB + (tid & 3) * 32;
    const uint32_t bdst0 = sbase + A_BYTES + brow * ASTRB + (tid & 1) * 64;

    auto fill = [&](int s, int k0) {
        uint32_t ad = adst0 + s * STAGE_B;
        #pragma unroll
        for (int j = 0; j < 2; j++) cpa16(ad + j * 16, srcA + k0 + j * 8, avalid);
        uint32_t bd = bdst0 + s * STAGE_B;
        #pragma unroll
        for (int j = 0; j < 4; j++) cpa16(bd + j * 16, srcB + k0 + j * 8, 16);
        CP_COMMIT();
    };

    fill(0, 0); fill(1, 64); fill(2, 128);

    float acc[2][8][4] = {};
    GEMM_FRAGS
    GEMM_MAINLOOP(D_IN / 64)
    __syncthreads();

    float* st = (float*)smem;   // [128][EPI_STR]
    GEMM_EPI_STAGE(st)
    __syncthreads();

    __half* Out = z ? g_eact : g_act;
    #pragma unroll
    for (int i = 0; i < 8; i++) {
        int f = tid + i * 512;
        int r = f >> 5, c4 = f & 31;            // 32 x 4-half chunks = 128 cols
        if (r < nrows) {
            float4 gg = *(float4*)(st + r * EPI_STR + c4 * 4);
            float4 vv = *(float4*)(st + r * EPI_STR + 128 + c4 * 4);
            __half2 h0 = __floats2half2_rn(gg.x / (1.f + __expf(-gg.x)) * vv.x,
                                           gg.y / (1.f + __expf(-gg.y)) * vv.y);
            __half2 h1 = __floats2half2_rn(gg.z / (1.f + __expf(-gg.z)) * vv.z,
                                           gg.w / (1.f + __expf(-gg.w)) * vv.w);
            uint32_t u0 = *(uint32_t*)&h0, u1 = *(uint32_t*)&h1;
            *(uint2*)(Out + (size_t)(rowStart + r) * HID + colBase + c4 * 4) =
                make_uint2(u0, u1);
        }
    }
}

// ============================================================================
// kernel 5: GEMM w3 (+ fused routing weight), merged z, K=512, fp16 output
// ============================================================================
__global__ __launch_bounds__(512, 1) void gemm3_mma()
{
    const int z = blockIdx.z;
    int rowStart, nrows;
    const __half* W;
    if (z == 0) {
        rowStart = blockIdx.y * 128;
        if (rowStart >= T_TOK) return;
        nrows = min(128, T_TOK - rowStart);
        W = g_w3s;
    } else {
        int e = z - 1;
        int re = g_off[e + 1];
        rowStart = g_off[e] + blockIdx.y * 128;
        if (rowStart >= re) return;
        nrows = min(128, re - rowStart);
        W = g_w3e + (size_t)e * LLM * HID;
    }
    const int colBase = blockIdx.x * 256;
    const __half* Act = z ? g_eact : g_act;

    extern __shared__ __align__(16) char smem[];
    const uint32_t sbase = smem_u32(smem);
    const int tid = threadIdx.x;

    const int arow = tid >> 2;
    const uint32_t avalid = (arow < nrows) ? 16 : 0;
    const __half* srcA = Act + (size_t)(rowStart + min(arow, nrows - 1)) * HID + (tid & 3) * 16;
    const int brow = tid >> 1;
    const __half* srcB = W + (size_t)(colBase + brow) * HID + (tid & 1) * 32;
    const uint32_t adst0 = sbase + arow * ASTRB + (tid & 3) * 32;
    const uint32_t bdst0 = sbase + A_BYTES + brow * ASTRB + (tid & 1) * 64;

    auto fill = [&](int s, int k0) {
        uint32_t ad = adst0 + s * STAGE_B;
        #pragma unroll
        for (int j = 0; j < 2; j++) cpa16(ad + j * 16, srcA + k0 + j * 8, avalid);
        uint32_t bd = bdst0 + s * STAGE_B;
        #pragma unroll
        for (int j = 0; j < 4; j++) cpa16(bd + j * 16, srcB + k0 + j * 8, 16);
        CP_COMMIT();
    };

    fill(0, 0); fill(1, 64); fill(2, 128);

    float acc[2][8][4] = {};
    GEMM_FRAGS
    GEMM_MAINLOOP(HID / 64)
    __syncthreads();

    float* st = (float*)smem;   // [128][EPI_STR]
    GEMM_EPI_STAGE(st)
    __syncthreads();

    __half* Out = z ? g_eo : g_shared;
    #pragma unroll
    for (int i = 0; i < 8; i++) {
        int f = tid + i * 512;
        int r = f >> 5, ch = f & 31;            // 32 chunks of 8 halfs = 256 cols
        if (r < nrows) {
            float sc = z ? g_permw[rowStart + r] : 1.f;
            const float* s0 = st + r * EPI_STR + ch * 8;
            __half2 h0 = __floats2half2_rn(sc * s0[0], sc * s0[1]);
            __half2 h1 = __floats2half2_rn(sc * s0[2], sc * s0[3]);
            __half2 h2 = __floats2half2_rn(sc * s0[4], sc * s0[5]);
            __half2 h3 = __floats2half2_rn(sc * s0[6], sc * s0[7]);
            uint4 u;
            u.x = *(uint32_t*)&h0; u.y = *(uint32_t*)&h1;
            u.z = *(uint32_t*)&h2; u.w = *(uint32_t*)&h3;
            *(uint4*)(Out + (size_t)(rowStart + r) * LLM + colBase + ch * 8) = u;
        }
    }
}

// ---------------- kernel 6: combine + LN_post (fp16 inputs) ------------------
__device__ __forceinline__ void blockReduce2(float& sum, float& sq) {
    __shared__ float ss[8], sv[8];
    #pragma unroll
    for (int o = 16; o > 0; o >>= 1) {
        sum += __shfl_down_sync(0xFFFFFFFFu, sum, o);
        sq  += __shfl_down_sync(0xFFFFFFFFu, sq,  o);
    }
    int w = threadIdx.x >> 5, l = threadIdx.x & 31;
    if (l == 0) { ss[w] = sum; sv[w] = sq; }
    __syncthreads();
    if (w == 0) {
        sum = (l < 8) ? ss[l] : 0.f;
        sq  = (l < 8) ? sv[l] : 0.f;
        #pragma unroll
        for (int o = 4; o > 0; o >>= 1) {
            sum += __shfl_down_sync(0xFFFFFFFFu, sum, o);
            sq  += __shfl_down_sync(0xFFFFFFFFu, sq,  o);
        }
        if (l == 0) { ss[0] = sum; sv[0] = sq; }
    }
    __syncthreads();
    sum = ss[0]; sq = sv[0];
}

__global__ __launch_bounds__(256) void ln_post_kernel(
    const float* __restrict__ lng, const float* __restrict__ lnb,
    float* __restrict__ out)
{
    int t = blockIdx.x;
    int tid = threadIdx.x;
    int p0 = g_pos[2 * t + 0], p1 = g_pos[2 * t + 1];
    const __half2* sh = (const __half2*)(g_shared + (size_t)t * LLM);
    const __half2* e0 = (const __half2*)(g_eo + (size_t)p0 * LLM);
    const __half2* e1 = (const __half2*)(g_eo + (size_t)p1 * LLM);
    float2 v[4];
    float sum = 0.f, sq = 0.f;
    #pragma unroll
    for (int i = 0; i < 4; i++) {
        int j = tid + i * 256;          // half2 index, j < 1024
        float2 a = __half22float2(sh[j]);
        float2 b = __half22float2(e0[j]);
        float2 c = __half22float2(e1[j]);
        float2 val = make_float2(a.x + b.x + c.x, a.y + b.y + c.y);
        v[i] = val;
        sum += val.x + val.y;
        sq += val.x * val.x + val.y * val.y;
    }
    blockReduce2(sum, sq);
    float m = sum * (1.f / LLM);
    float var = sq * (1.f / LLM) - m * m;
    float rinv = rsqrtf(var + 1e-6f);
    float* orow = out + (size_t)t * LLM;
    #pragma unroll
    for (int i = 0; i < 4; i++) {
        int j = tid + i * 256;
        float2 gv = ((const float2*)lng)[j];
        float2 bv = ((const float2*)lnb)[j];
        float2 o;
        o.x = (v[i].x - m) * rinv * gv.x + bv.x;
        o.y = (v[i].y - m) * rinv * gv.y + bv.y;
        *(float2*)(orow + 2 * j) = o;
    }
}

// ---------------- launcher ----------------------------------------------------
extern "C" void kernel_launch(void* const* d_in, const int* in_sizes, int n_in,
                              void* d_out, int out_size)
{
    const float* x           = (const float*)d_in[0];
    const float* ln_pre_g    = (const float*)d_in[1];
    const float* ln_pre_b    = (const float*)d_in[2];
    const float* router_w    = (const float*)d_in[3];
    const float* router_b    = (const float*)d_in[4];
    const float* shared_w12  = (const float*)d_in[5];
    const float* shared_w3   = (const float*)d_in[6];
    const float* experts_w12 = (const float*)d_in[7];
    const float* experts_w3  = (const float*)d_in[8];
    const float* ln_post_g   = (const float*)d_in[9];
    const float* ln_post_b   = (const float*)d_in[10];
    float* out = (float*)d_out;

    const int RW_SMEM = NE * D_IN * 4;  // 80 KB
    cudaFuncSetAttribute(gemm12_mma, cudaFuncAttributeMaxDynamicSharedMemorySize, SMEM_DYN);
    cudaFuncSetAttribute(gemm3_mma,  cudaFuncAttributeMaxDynamicSharedMemorySize, SMEM_DYN);
    cudaFuncSetAttribute(ln_router_kernel, cudaFuncAttributeMaxDynamicSharedMemorySize, RW_SMEM);

    cvt_weights<<<4096, 256>>>((const float4*)shared_w12, (const float4*)shared_w3,
                               (const float4*)experts_w12, (const float4*)experts_w3);
    ln_router_kernel<<<(T_TOK + 63) / 64, 256, RW_SMEM>>>(x, ln_pre_g, ln_pre_b,
                                                          router_w, router_b);
    scan_kernel<<<1, 32>>>();
    build_kernel<<<(T_TOK + 255) / 256, 256>>>();

    const int MT = (T_TOK + 127) / 128;   // 94 (also covers worst-case expert)
    gemm12_mma<<<dim3(HID / 128, MT, NE + 1), 512, SMEM_DYN>>>();
    gemm3_mma <<<dim3(LLM / 256, MT, NE + 1), 512, SMEM_DYN>>>();

    ln_post_kernel<<<T_TOK, 256>>>(ln_post_g, ln_post_b, out);
}